// round 1
// baseline (speedup 1.0000x reference)
#include <cuda_runtime.h>
#include <math.h>
#include <stdint.h>

// Problem constants
#define Nn    2000
#define DIN   2
#define DOUT  64
#define EDIM  16
#define KCH   3
#define Bb    64
#define CIN   66                  // DIN+DOUT
#define CCOLS (Bb*CIN)            // 4224
#define KI    (KCH*CIN)           // 198
#define ORES  (2*DOUT)            // 128
#define WRJ   (KI*ORES)           // 25344
#define WUJ   (KI*DOUT)           // 12672

// ---------------- scratch (device globals; no allocation allowed) ----------
__device__ float g_A [Nn*Nn];                 // 16 MB
__device__ float g_X0[Nn*CCOLS];              // 33.8 MB (xs, later cand in-place)
__device__ float g_Y1[Nn*CCOLS];              // 33.8 MB
__device__ float g_Y2[Nn*CCOLS];              // 33.8 MB
__device__ float g_Wr[(size_t)Nn*WRJ];        // 202.8 MB
__device__ float g_Wu[(size_t)Nn*WUJ];        // 101.4 MB
__device__ float g_Z [(size_t)Nn*Bb*DOUT];    // 32.8 MB

// ---------------- adjacency: A[m,:] = softmax(relu(emb[m]·embᵀ)) ----------
__global__ __launch_bounds__(256) void adj_softmax(const float* __restrict__ emb)
{
    __shared__ float row[Nn];
    __shared__ float em[EDIM];
    __shared__ float red[256];
    int m = blockIdx.x, tid = threadIdx.x;
    if (tid < EDIM) em[tid] = emb[m*EDIM + tid];
    __syncthreads();
    float lmax = -1e30f;
    for (int n = tid; n < Nn; n += 256) {
        float d = 0.f;
        #pragma unroll
        for (int e = 0; e < EDIM; e++) d += em[e] * emb[n*EDIM + e];
        d = fmaxf(d, 0.f);
        row[n] = d;
        lmax = fmaxf(lmax, d);
    }
    red[tid] = lmax; __syncthreads();
    for (int s = 128; s > 0; s >>= 1) {
        if (tid < s) red[tid] = fmaxf(red[tid], red[tid + s]);
        __syncthreads();
    }
    float mx = red[0];
    __syncthreads();
    float ls = 0.f;
    for (int n = tid; n < Nn; n += 256) {
        float e0 = expf(row[n] - mx);
        row[n] = e0;
        ls += e0;
    }
    red[tid] = ls; __syncthreads();
    for (int s = 128; s > 0; s >>= 1) {
        if (tid < s) red[tid] += red[tid + s];
        __syncthreads();
    }
    float inv = 1.f / red[0];
    for (int n = tid; n < Nn; n += 256) g_A[m*Nn + n] = row[n] * inv;
}

// ---------------- pack xs = concat(x, state) as [N, B*66] ------------------
__global__ __launch_bounds__(256) void pack_x0(const float* __restrict__ x,
                                               const float* __restrict__ st)
{
    int idx = blockIdx.x * 256 + threadIdx.x;
    if (idx >= Nn*CCOLS) return;
    int n = idx / CCOLS;
    int c = idx - n*CCOLS;
    int b = c / CIN, i = c - b*CIN;
    float v = (i < DIN) ? x[((size_t)b*Nn + n)*DIN + i]
                        : st[((size_t)b*Nn + n)*DOUT + (i - DIN)];
    g_X0[idx] = v;
}

// ---------------- SGEMM: C = alpha*A@B + beta*Csrc  (M x N x K) ------------
// BM=BN=128, BK=16, 256 threads, 8x8 per thread
__global__ __launch_bounds__(256) void sgemm128(
    const float* __restrict__ A, const float* __restrict__ B,
    const float* __restrict__ Csrc, float* __restrict__ C,
    int M, int N, int K, float alpha, float beta)
{
    __shared__ float As[16][132];   // transposed, padded
    __shared__ float Bs[16][128];

    int tid = threadIdx.x;
    int tx = tid & 15, ty = tid >> 4;
    int row0 = blockIdx.y * 128, col0 = blockIdx.x * 128;

    float acc[8][8] = {};
    int aRow = tid >> 2;            // 0..63
    int aCol = (tid & 3) << 2;      // 0,4,8,12
    int bRow = tid >> 5;            // 0..7
    int bCol = (tid & 31) << 2;

    for (int k0 = 0; k0 < K; k0 += 16) {
        #pragma unroll
        for (int h = 0; h < 2; h++) {
            int r = row0 + aRow + h*64;
            float4 v = make_float4(0.f, 0.f, 0.f, 0.f);
            if (r < M) v = *(const float4*)&A[(size_t)r*K + k0 + aCol];
            As[aCol+0][aRow + h*64] = v.x;
            As[aCol+1][aRow + h*64] = v.y;
            As[aCol+2][aRow + h*64] = v.z;
            As[aCol+3][aRow + h*64] = v.w;
        }
        #pragma unroll
        for (int h = 0; h < 2; h++) {
            int r = k0 + bRow + h*8;
            *(float4*)&Bs[bRow + h*8][bCol] =
                *(const float4*)&B[(size_t)r*N + col0 + bCol];
        }
        __syncthreads();
        #pragma unroll
        for (int kk = 0; kk < 16; kk++) {
            float4 a0 = *(const float4*)&As[kk][ty*8];
            float4 a1 = *(const float4*)&As[kk][ty*8 + 4];
            float4 b0 = *(const float4*)&Bs[kk][tx*8];
            float4 b1 = *(const float4*)&Bs[kk][tx*8 + 4];
            float a[8] = {a0.x,a0.y,a0.z,a0.w,a1.x,a1.y,a1.z,a1.w};
            float b[8] = {b0.x,b0.y,b0.z,b0.w,b1.x,b1.y,b1.z,b1.w};
            #pragma unroll
            for (int i2 = 0; i2 < 8; i2++)
                #pragma unroll
                for (int j2 = 0; j2 < 8; j2++)
                    acc[i2][j2] += a[i2] * b[j2];
        }
        __syncthreads();
    }
    #pragma unroll
    for (int i2 = 0; i2 < 8; i2++) {
        int r = row0 + ty*8 + i2;
        if (r >= M) continue;
        #pragma unroll
        for (int j2 = 0; j2 < 8; j2 += 4) {
            size_t cidx = (size_t)r*N + col0 + tx*8 + j2;
            float4 o;
            o.x = alpha*acc[i2][j2+0];
            o.y = alpha*acc[i2][j2+1];
            o.z = alpha*acc[i2][j2+2];
            o.w = alpha*acc[i2][j2+3];
            if (beta != 0.f) {
                float4 cs = *(const float4*)&Csrc[cidx];
                o.x += beta*cs.x; o.y += beta*cs.y;
                o.z += beta*cs.z; o.w += beta*cs.w;
            }
            *(float4*)&C[cidx] = o;
        }
    }
}

// ---------------- per-node weight mix: out[n,j] = sum_e emb[n,e]*W[e,j] ----
__global__ __launch_bounds__(256) void mix_weights(
    const float* __restrict__ emb, const float* __restrict__ W,
    float* __restrict__ out, int J)
{
    __shared__ float Ws[EDIM][256];
    __shared__ float Em[32][EDIM];
    int tid = threadIdx.x;
    int j = blockIdx.x * 256 + tid;
    int n0 = blockIdx.y * 32;
    bool jok = (j < J);
    #pragma unroll
    for (int e = 0; e < EDIM; e++)
        Ws[e][tid] = jok ? W[(size_t)e*J + j] : 0.f;
    for (int t = tid; t < 32*EDIM; t += 256) {
        int nn = t >> 4, e = t & 15;
        int n = n0 + nn;
        Em[nn][e] = (n < Nn) ? emb[n*EDIM + e] : 0.f;
    }
    __syncthreads();
    if (!jok) return;
    for (int nn = 0; nn < 32; nn++) {
        int n = n0 + nn;
        if (n >= Nn) break;
        float acc = 0.f;
        #pragma unroll
        for (int e = 0; e < EDIM; e++) acc += Em[nn][e] * Ws[e][tid];
        out[(size_t)n*J + j] = acc;
    }
}

// ---------------- gate: z_r = sigmoid(xg·Wr_n + br), writes Z and cand -----
// one block per node; 256 threads; 64(b) x 128(o) outputs, K=198
#define XGS 65
__global__ __launch_bounds__(256) void gate_kernel(
    const float* __restrict__ emb, const float* __restrict__ b_reset,
    const float* __restrict__ st)
{
    extern __shared__ float sh[];
    float* xg_s = sh;            // 198*65 -> padded region of 12872
    float* ws   = sh + 12872;    // 6*128 = 768 (16B aligned)
    float* br   = ws + 768;      // 128
    float* em   = br + 128;      // 16

    int n = blockIdx.x, tid = threadIdx.x;
    if (tid < EDIM) em[tid] = emb[n*EDIM + tid];
    __syncthreads();
    if (tid < ORES) {
        float a = 0.f;
        #pragma unroll
        for (int e = 0; e < EDIM; e++) a += em[e] * b_reset[e*ORES + tid];
        br[tid] = a;
    }
    const float* r0 = g_X0 + (size_t)n*CCOLS;
    const float* r1 = g_Y1 + (size_t)n*CCOLS;
    const float* r2 = g_Y2 + (size_t)n*CCOLS;
    for (int c = tid; c < CCOLS; c += 256) {
        int b = c / CIN, i = c - b*CIN;
        xg_s[(0*CIN + i)*XGS + b] = r0[c];
        xg_s[(1*CIN + i)*XGS + b] = r1[c];
        xg_s[(2*CIN + i)*XGS + b] = r2[c];
    }
    __syncthreads();

    int tx = tid & 15, ty = tid >> 4;
    float acc[4][8] = {};
    const float* wr = g_Wr + (size_t)n*WRJ;
    for (int kk0 = 0; kk0 < KI; kk0 += 6) {
        __syncthreads();
        #pragma unroll
        for (int t = 0; t < 3; t++)
            ws[tid + t*256] = wr[kk0*ORES + tid + t*256];
        __syncthreads();
        #pragma unroll
        for (int kk = 0; kk < 6; kk++) {
            const float* xr = &xg_s[(kk0 + kk)*XGS + ty*4];
            float a0 = xr[0], a1 = xr[1], a2 = xr[2], a3 = xr[3];
            float4 w0 = *(const float4*)&ws[kk*ORES + tx*8];
            float4 w1 = *(const float4*)&ws[kk*ORES + tx*8 + 4];
            float w[8] = {w0.x,w0.y,w0.z,w0.w,w1.x,w1.y,w1.z,w1.w};
            #pragma unroll
            for (int j2 = 0; j2 < 8; j2++) {
                acc[0][j2] += a0 * w[j2];
                acc[1][j2] += a1 * w[j2];
                acc[2][j2] += a2 * w[j2];
                acc[3][j2] += a3 * w[j2];
            }
        }
    }
    __syncthreads();
    #pragma unroll
    for (int bb = 0; bb < 4; bb++) {
        int b = ty*4 + bb;
        #pragma unroll
        for (int oo = 0; oo < 8; oo++) {
            int o = tx*8 + oo;
            float zr = 1.f / (1.f + expf(-(acc[bb][oo] + br[o])));
            if (o < DOUT) {
                g_Z[((size_t)n*Bb + b)*DOUT + o] = zr;
            } else {
                int od = o - DOUT;
                float rs = zr * st[((size_t)b*Nn + n)*DOUT + od];
                g_X0[(size_t)n*CCOLS + b*CIN + DIN + od] = rs;   // cand in place
            }
        }
    }
}

// ---------------- final: hc = tanh(xg2·Wu_n + bu); out = z*s + (1-z)*hc ----
__global__ __launch_bounds__(256) void final_kernel(
    const float* __restrict__ emb, const float* __restrict__ b_update,
    const float* __restrict__ st, float* __restrict__ out)
{
    extern __shared__ float sh[];
    float* xg_s = sh;            // 12872
    float* ws   = sh + 12872;    // 6*64 = 384
    float* bu   = ws + 384;      // 64
    float* em   = bu + 64;       // 16

    int n = blockIdx.x, tid = threadIdx.x;
    if (tid < EDIM) em[tid] = emb[n*EDIM + tid];
    __syncthreads();
    if (tid < DOUT) {
        float a = 0.f;
        #pragma unroll
        for (int e = 0; e < EDIM; e++) a += em[e] * b_update[e*DOUT + tid];
        bu[tid] = a;
    }
    const float* r0 = g_X0 + (size_t)n*CCOLS;
    const float* r1 = g_Y1 + (size_t)n*CCOLS;
    const float* r2 = g_Y2 + (size_t)n*CCOLS;
    for (int c = tid; c < CCOLS; c += 256) {
        int b = c / CIN, i = c - b*CIN;
        xg_s[(0*CIN + i)*XGS + b] = r0[c];
        xg_s[(1*CIN + i)*XGS + b] = r1[c];
        xg_s[(2*CIN + i)*XGS + b] = r2[c];
    }
    __syncthreads();

    int tx = tid & 15, ty = tid >> 4;   // tx: o-tile (16x4=64), ty: b-tile (16x4=64)
    float acc[4][4] = {};
    const float* wu = g_Wu + (size_t)n*WUJ;
    for (int kk0 = 0; kk0 < KI; kk0 += 6) {
        __syncthreads();
        for (int idx = tid; idx < 6*DOUT; idx += 256)
            ws[idx] = wu[kk0*DOUT + idx];
        __syncthreads();
        #pragma unroll
        for (int kk = 0; kk < 6; kk++) {
            const float* xr = &xg_s[(kk0 + kk)*XGS + ty*4];
            float a0 = xr[0], a1 = xr[1], a2 = xr[2], a3 = xr[3];
            float4 w0 = *(const float4*)&ws[kk*DOUT + tx*4];
            float w[4] = {w0.x, w0.y, w0.z, w0.w};
            #pragma unroll
            for (int j2 = 0; j2 < 4; j2++) {
                acc[0][j2] += a0 * w[j2];
                acc[1][j2] += a1 * w[j2];
                acc[2][j2] += a2 * w[j2];
                acc[3][j2] += a3 * w[j2];
            }
        }
    }
    __syncthreads();
    #pragma unroll
    for (int bb = 0; bb < 4; bb++) {
        int b = ty*4 + bb;
        #pragma unroll
        for (int oo = 0; oo < 4; oo++) {
            int o = tx*4 + oo;
            float hc = tanhf(acc[bb][oo] + bu[o]);
            float z  = g_Z[((size_t)n*Bb + b)*DOUT + o];
            float s  = st[((size_t)b*Nn + n)*DOUT + o];
            out[((size_t)b*Nn + n)*DOUT + o] = z*s + (1.f - z)*hc;
        }
    }
}

// ---------------- launch ---------------------------------------------------
extern "C" void kernel_launch(void* const* d_in, const int* in_sizes, int n_in,
                              void* d_out, int out_size)
{
    const float* x    = (const float*)d_in[0];
    const float* st   = (const float*)d_in[1];
    const float* emb  = (const float*)d_in[2];
    const float* Wr_w = (const float*)d_in[3];
    const float* Wu_w = (const float*)d_in[4];
    const float* br_b = (const float*)d_in[5];
    const float* bu_b = (const float*)d_in[6];
    float* out = (float*)d_out;

    float *pA, *pX0, *pY1, *pY2, *pWr, *pWu;
    cudaGetSymbolAddress((void**)&pA,  g_A);
    cudaGetSymbolAddress((void**)&pX0, g_X0);
    cudaGetSymbolAddress((void**)&pY1, g_Y1);
    cudaGetSymbolAddress((void**)&pY2, g_Y2);
    cudaGetSymbolAddress((void**)&pWr, g_Wr);
    cudaGetSymbolAddress((void**)&pWu, g_Wu);

    const int gate_smem  = (12872 + 768 + 128 + 16) * 4;
    const int final_smem = (12872 + 384 + 64 + 16) * 4;
    cudaFuncSetAttribute(gate_kernel,  cudaFuncAttributeMaxDynamicSharedMemorySize, gate_smem);
    cudaFuncSetAttribute(final_kernel, cudaFuncAttributeMaxDynamicSharedMemorySize, final_smem);

    dim3 gGemm(CCOLS/128, (Nn + 127)/128);   // (33, 16)

    // adjacency + per-node weights (independent of conv)
    adj_softmax<<<Nn, 256>>>(emb);
    mix_weights<<<dim3((WRJ + 255)/256, (Nn + 31)/32), 256>>>(emb, Wr_w, pWr, WRJ);
    mix_weights<<<dim3((WUJ + 255)/256, (Nn + 31)/32), 256>>>(emb, Wu_w, pWu, WUJ);

    // pass 1: conv of xs
    pack_x0<<<(Nn*CCOLS + 255)/256, 256>>>(x, st);
    sgemm128<<<gGemm, 256>>>(pA, pX0, pX0, pY1, Nn, CCOLS, Nn, 1.f, 0.f);
    sgemm128<<<gGemm, 256>>>(pA, pY1, pX0, pY2, Nn, CCOLS, Nn, 2.f, -1.f);

    // gates: z, r; writes cand into X0 in place
    gate_kernel<<<Nn, 256, gate_smem>>>(emb, br_b, st);

    // pass 2: conv of cand
    sgemm128<<<gGemm, 256>>>(pA, pX0, pX0, pY1, Nn, CCOLS, Nn, 1.f, 0.f);
    sgemm128<<<gGemm, 256>>>(pA, pY1, pX0, pY2, Nn, CCOLS, Nn, 2.f, -1.f);

    // candidate + combine
    final_kernel<<<Nn, 256, final_smem>>>(emb, bu_b, st, out);
}

// round 2
// speedup vs baseline: 1.9012x; 1.9012x over previous
#include <cuda_runtime.h>
#include <cuda_bf16.h>
#include <math.h>
#include <stdint.h>

typedef unsigned int u32;
typedef __nv_bfloat16 bf16;

// Problem constants
#define Nn    2000
#define DIN   2
#define DOUT  64
#define EDIM  16
#define KCH   3
#define Bb    64
#define CIN   66                  // DIN+DOUT
#define CCOLS (Bb*CIN)            // 4224
#define KI    (KCH*CIN)           // 198
#define ORES  (2*DOUT)            // 128
#define WRJ   (KI*ORES)           // 25344
#define WUJ   (KI*DOUT)           // 12672

// ---------------- scratch (device globals; no allocation allowed) ----------
__device__ __align__(256) bf16  g_Ah[(size_t)Nn*Nn];
__device__ __align__(256) bf16  g_Al[(size_t)Nn*Nn];
__device__ __align__(256) float g_X0[(size_t)Nn*CCOLS];
__device__ __align__(256) bf16  g_Xh[(size_t)Nn*CCOLS];
__device__ __align__(256) bf16  g_Xl[(size_t)Nn*CCOLS];
__device__ __align__(256) float g_Y1[(size_t)Nn*CCOLS];
__device__ __align__(256) bf16  g_Y1h[(size_t)Nn*CCOLS];
__device__ __align__(256) bf16  g_Y1l[(size_t)Nn*CCOLS];
__device__ __align__(256) float g_Y2[(size_t)Nn*CCOLS];
__device__ __align__(256) float g_Wr[(size_t)Nn*WRJ];
__device__ __align__(256) float g_Wu[(size_t)Nn*WUJ];
__device__ __align__(256) float g_Z [(size_t)Nn*Bb*DOUT];

__device__ __forceinline__ void split2(float v, bf16& h, bf16& l)
{
    h = __float2bfloat16(v);
    l = __float2bfloat16(v - __bfloat162float(h));
}

// ---------------- adjacency: softmax(relu(emb·embᵀ)) row-wise, split bf16 --
__global__ __launch_bounds__(256) void adj_softmax(const float* __restrict__ emb)
{
    __shared__ float row[Nn];
    __shared__ float em[EDIM];
    __shared__ float red[256];
    int m = blockIdx.x, tid = threadIdx.x;
    if (tid < EDIM) em[tid] = emb[m*EDIM + tid];
    __syncthreads();
    float lmax = -1e30f;
    for (int n = tid; n < Nn; n += 256) {
        float d = 0.f;
        #pragma unroll
        for (int e = 0; e < EDIM; e++) d += em[e] * emb[n*EDIM + e];
        d = fmaxf(d, 0.f);
        row[n] = d;
        lmax = fmaxf(lmax, d);
    }
    red[tid] = lmax; __syncthreads();
    for (int s = 128; s > 0; s >>= 1) {
        if (tid < s) red[tid] = fmaxf(red[tid], red[tid + s]);
        __syncthreads();
    }
    float mx = red[0];
    __syncthreads();
    float ls = 0.f;
    for (int n = tid; n < Nn; n += 256) {
        float e0 = expf(row[n] - mx);
        row[n] = e0;
        ls += e0;
    }
    red[tid] = ls; __syncthreads();
    for (int s = 128; s > 0; s >>= 1) {
        if (tid < s) red[tid] += red[tid + s];
        __syncthreads();
    }
    float inv = 1.f / red[0];
    for (int n = tid; n < Nn; n += 256) {
        float v = row[n] * inv;
        bf16 h, l; split2(v, h, l);
        g_Ah[(size_t)m*Nn + n] = h;
        g_Al[(size_t)m*Nn + n] = l;
    }
}

// ---------------- pack xs = concat(x, state) as [N, B*66] + split ----------
__global__ __launch_bounds__(256) void pack_x0(const float* __restrict__ x,
                                               const float* __restrict__ st)
{
    int idx = blockIdx.x * 256 + threadIdx.x;
    if (idx >= Nn*CCOLS) return;
    int n = idx / CCOLS;
    int c = idx - n*CCOLS;
    int b = c / CIN, i = c - b*CIN;
    float v = (i < DIN) ? x[((size_t)b*Nn + n)*DIN + i]
                        : st[((size_t)b*Nn + n)*DOUT + (i - DIN)];
    g_X0[idx] = v;
    bf16 h, l; split2(v, h, l);
    g_Xh[idx] = h;
    g_Xl[idx] = l;
}

// ---------------- tensor-core split-bf16 GEMM ------------------------------
// C[M,N] = alpha*(A@B) + beta*Csrc, where A = Ah+Al, B = Bh+Bl (bf16 splits).
// Tiles: 128x128x32, 8 warps (warp layout 4(M) x 2(N), warp tile 32x64).
#define ASTR 40    // halves, padded
#define BSTR 136   // halves, padded
#define A_STAGE_B 10240      // 128*40*2
#define B_STAGE_B 8704       // 32*136*2
#define STAGE_B   37888      // 2*A + 2*B
#define GSMEM_B   75776      // 2 stages

#define LDSM4(R0,R1,R2,R3,addr) \
    asm volatile("ldmatrix.sync.aligned.m8n8.x4.shared.b16 {%0,%1,%2,%3},[%4];" \
        : "=r"(R0),"=r"(R1),"=r"(R2),"=r"(R3) : "r"(addr))
#define LDSM4T(R0,R1,R2,R3,addr) \
    asm volatile("ldmatrix.sync.aligned.m8n8.x4.trans.shared.b16 {%0,%1,%2,%3},[%4];" \
        : "=r"(R0),"=r"(R1),"=r"(R2),"=r"(R3) : "r"(addr))
#define MMA16816(C,A,B0,B1) \
    asm volatile("mma.sync.aligned.m16n8k16.row.col.f32.bf16.bf16.f32 " \
        "{%0,%1,%2,%3},{%4,%5,%6,%7},{%8,%9},{%0,%1,%2,%3};" \
        : "+f"(C[0]),"+f"(C[1]),"+f"(C[2]),"+f"(C[3]) \
        : "r"(A[0]),"r"(A[1]),"r"(A[2]),"r"(A[3]),"r"(B0),"r"(B1))
#define CP16(saddr,gptr) \
    asm volatile("cp.async.cg.shared.global [%0], [%1], 16;" :: "r"(saddr), "l"(gptr))

__global__ __launch_bounds__(256) void mma_gemm(
    const bf16* __restrict__ Ah, const bf16* __restrict__ Al,
    const bf16* __restrict__ Bh, const bf16* __restrict__ Bl,
    const float* __restrict__ Csrc, float* __restrict__ C,
    bf16* __restrict__ Ch, bf16* __restrict__ Cl,
    int M, int N, int K, float alpha, float beta, int writeSplit)
{
    extern __shared__ __align__(16) char smem_raw[];
    const u32 sbase = (u32)__cvta_generic_to_shared(smem_raw);

    int tid  = threadIdx.x;
    int lane = tid & 31;
    int warp = tid >> 5;
    int wm = warp & 3;        // 0..3 -> M offset wm*32
    int wn = warp >> 2;       // 0..1 -> N offset wn*64
    int lrow = lane & 7;
    int lsel = lane >> 3;     // 0..3

    int m0 = blockIdx.y * 128;
    int n0 = blockIdx.x * 128;

    float acc[2][8][4];
    #pragma unroll
    for (int i = 0; i < 2; i++)
        #pragma unroll
        for (int j = 0; j < 8; j++)
            #pragma unroll
            for (int r = 0; r < 4; r++) acc[i][j][r] = 0.f;

    const float4 z4 = make_float4(0.f,0.f,0.f,0.f);

    auto load_stage = [&](int stage, int k0) {
        // A tiles: 128 x 32, hi/lo
        #pragma unroll
        for (int hl = 0; hl < 2; hl++) {
            const bf16* gA = hl ? Al : Ah;
            #pragma unroll
            for (int t = 0; t < 2; t++) {
                int idx = tid + t*256;
                int row = idx >> 2;
                int col = (idx & 3) << 3;
                int off = stage*STAGE_B + hl*A_STAGE_B + (row*ASTR + col)*2;
                int gr = m0 + row;
                if (gr < M && (k0 + col) < K) {
                    CP16(sbase + off, (const void*)(gA + (size_t)gr*K + k0 + col));
                } else {
                    *(float4*)(smem_raw + off) = z4;
                }
            }
        }
        // B tiles: 32 x 128, hi/lo
        #pragma unroll
        for (int hl = 0; hl < 2; hl++) {
            const bf16* gB = hl ? Bl : Bh;
            #pragma unroll
            for (int t = 0; t < 2; t++) {
                int idx = tid + t*256;
                int row = idx >> 4;
                int col = (idx & 15) << 3;
                int off = stage*STAGE_B + 2*A_STAGE_B + hl*B_STAGE_B + (row*BSTR + col)*2;
                int gk = k0 + row;
                if (gk < K) {
                    CP16(sbase + off, (const void*)(gB + (size_t)gk*N + n0 + col));
                } else {
                    *(float4*)(smem_raw + off) = z4;
                }
            }
        }
    };

    int KT = (K + 31) / 32;
    load_stage(0, 0);
    asm volatile("cp.async.commit_group;");

    for (int ks = 0; ks < KT; ks++) {
        asm volatile("cp.async.wait_group 0;");
        __syncthreads();
        int cur = ks & 1;
        if (ks + 1 < KT) {
            load_stage(cur ^ 1, (ks + 1) * 32);
            asm volatile("cp.async.commit_group;");
        }
        // compute on stage cur
        #pragma unroll
        for (int kk = 0; kk < 32; kk += 16) {
            u32 ah[2][4], al[2][4], bh[8][2], bl[8][2];
            #pragma unroll
            for (int mt = 0; mt < 2; mt++) {
                int row = wm*32 + mt*16 + lrow + (lsel & 1)*8;
                int col = kk + (lsel >> 1)*8;
                u32 a0 = sbase + cur*STAGE_B + (row*ASTR + col)*2;
                LDSM4(ah[mt][0], ah[mt][1], ah[mt][2], ah[mt][3], a0);
                u32 a1 = a0 + A_STAGE_B;
                LDSM4(al[mt][0], al[mt][1], al[mt][2], al[mt][3], a1);
            }
            #pragma unroll
            for (int p = 0; p < 4; p++) {
                int row = kk + lrow + (lsel & 1)*8;
                int col = wn*64 + p*16 + (lsel >> 1)*8;
                u32 b0 = sbase + cur*STAGE_B + 2*A_STAGE_B + (row*BSTR + col)*2;
                u32 t0,t1,t2,t3;
                LDSM4T(t0,t1,t2,t3,b0);
                bh[2*p][0]=t0; bh[2*p][1]=t1; bh[2*p+1][0]=t2; bh[2*p+1][1]=t3;
                u32 b1 = b0 + B_STAGE_B;
                LDSM4T(t0,t1,t2,t3,b1);
                bl[2*p][0]=t0; bl[2*p][1]=t1; bl[2*p+1][0]=t2; bl[2*p+1][1]=t3;
            }
            #pragma unroll
            for (int mt = 0; mt < 2; mt++)
                #pragma unroll
                for (int nt = 0; nt < 8; nt++) {
                    MMA16816(acc[mt][nt], ah[mt], bh[nt][0], bh[nt][1]);
                    MMA16816(acc[mt][nt], ah[mt], bl[nt][0], bl[nt][1]);
                    MMA16816(acc[mt][nt], al[mt], bh[nt][0], bh[nt][1]);
                }
        }
        __syncthreads();
    }

    // epilogue
    int group = lane >> 2, tg = lane & 3;
    #pragma unroll
    for (int mt = 0; mt < 2; mt++) {
        int rbase = m0 + wm*32 + mt*16 + group;
        #pragma unroll
        for (int half = 0; half < 2; half++) {
            int r = rbase + half*8;
            if (r >= M) continue;
            #pragma unroll
            for (int nt = 0; nt < 8; nt++) {
                int cidx0 = nt*8 + tg*2;
                int col = n0 + wn*64 + cidx0;
                size_t gi = (size_t)r*N + col;
                float v0 = alpha*acc[mt][nt][half*2+0];
                float v1 = alpha*acc[mt][nt][half*2+1];
                if (beta != 0.f) {
                    float2 cs = *(const float2*)&Csrc[gi];
                    v0 += beta*cs.x; v1 += beta*cs.y;
                }
                *(float2*)&C[gi] = make_float2(v0, v1);
                if (writeSplit) {
                    bf16 h0,l0,h1,l1;
                    split2(v0,h0,l0); split2(v1,h1,l1);
                    Ch[gi]   = h0; Ch[gi+1] = h1;
                    Cl[gi]   = l0; Cl[gi+1] = l1;
                }
            }
        }
    }
}

// ---------------- per-node weight mix: out[n,j] = sum_e emb[n,e]*W[e,j] ----
__global__ __launch_bounds__(256) void mix_weights(
    const float* __restrict__ emb, const float* __restrict__ W,
    float* __restrict__ out, int J)
{
    __shared__ float Ws[EDIM][256];
    __shared__ float Em[32][EDIM];
    int tid = threadIdx.x;
    int j = blockIdx.x * 256 + tid;
    int n0 = blockIdx.y * 32;
    bool jok = (j < J);
    #pragma unroll
    for (int e = 0; e < EDIM; e++)
        Ws[e][tid] = jok ? W[(size_t)e*J + j] : 0.f;
    for (int t = tid; t < 32*EDIM; t += 256) {
        int nn = t >> 4, e = t & 15;
        int n = n0 + nn;
        Em[nn][e] = (n < Nn) ? emb[n*EDIM + e] : 0.f;
    }
    __syncthreads();
    if (!jok) return;
    for (int nn = 0; nn < 32; nn++) {
        int n = n0 + nn;
        if (n >= Nn) break;
        float acc = 0.f;
        #pragma unroll
        for (int e = 0; e < EDIM; e++) acc += Em[nn][e] * Ws[e][tid];
        out[(size_t)n*J + j] = acc;
    }
}

// ---------------- gate: z_r = sigmoid(xg·Wr_n + br), writes Z and cand -----
#define XGS 65
__global__ __launch_bounds__(256) void gate_kernel(
    const float* __restrict__ emb, const float* __restrict__ b_reset,
    const float* __restrict__ st)
{
    extern __shared__ float sh[];
    float* xg_s = sh;            // 198*65 -> 12872 region
    float* ws   = sh + 12872;    // 6*128 = 768
    float* br   = ws + 768;      // 128
    float* em   = br + 128;      // 16

    int n = blockIdx.x, tid = threadIdx.x;
    if (tid < EDIM) em[tid] = emb[n*EDIM + tid];
    __syncthreads();
    if (tid < ORES) {
        float a = 0.f;
        #pragma unroll
        for (int e = 0; e < EDIM; e++) a += em[e] * b_reset[e*ORES + tid];
        br[tid] = a;
    }
    const float* r0 = g_X0 + (size_t)n*CCOLS;
    const float* r1 = g_Y1 + (size_t)n*CCOLS;
    const float* r2 = g_Y2 + (size_t)n*CCOLS;
    for (int c = tid; c < CCOLS; c += 256) {
        int b = c / CIN, i = c - b*CIN;
        xg_s[(0*CIN + i)*XGS + b] = r0[c];
        xg_s[(1*CIN + i)*XGS + b] = r1[c];
        xg_s[(2*CIN + i)*XGS + b] = r2[c];
    }
    __syncthreads();

    int tx = tid & 15, ty = tid >> 4;
    float acc[4][8] = {};
    const float* wr = g_Wr + (size_t)n*WRJ;
    for (int kk0 = 0; kk0 < KI; kk0 += 6) {
        __syncthreads();
        #pragma unroll
        for (int t = 0; t < 3; t++)
            ws[tid + t*256] = wr[kk0*ORES + tid + t*256];
        __syncthreads();
        #pragma unroll
        for (int kk = 0; kk < 6; kk++) {
            const float* xr = &xg_s[(kk0 + kk)*XGS + ty*4];
            float a0 = xr[0], a1 = xr[1], a2 = xr[2], a3 = xr[3];
            float4 w0 = *(const float4*)&ws[kk*ORES + tx*8];
            float4 w1 = *(const float4*)&ws[kk*ORES + tx*8 + 4];
            float w[8] = {w0.x,w0.y,w0.z,w0.w,w1.x,w1.y,w1.z,w1.w};
            #pragma unroll
            for (int j2 = 0; j2 < 8; j2++) {
                acc[0][j2] += a0 * w[j2];
                acc[1][j2] += a1 * w[j2];
                acc[2][j2] += a2 * w[j2];
                acc[3][j2] += a3 * w[j2];
            }
        }
    }
    __syncthreads();
    #pragma unroll
    for (int bb = 0; bb < 4; bb++) {
        int b = ty*4 + bb;
        #pragma unroll
        for (int oo = 0; oo < 8; oo++) {
            int o = tx*8 + oo;
            float zr = 1.f / (1.f + expf(-(acc[bb][oo] + br[o])));
            if (o < DOUT) {
                g_Z[((size_t)n*Bb + b)*DOUT + o] = zr;
            } else {
                int od = o - DOUT;
                float rs = zr * st[((size_t)b*Nn + n)*DOUT + od];
                size_t xi = (size_t)n*CCOLS + b*CIN + DIN + od;
                g_X0[xi] = rs;                      // cand fp32 in place
                bf16 h, l; split2(rs, h, l);
                g_Xh[xi] = h; g_Xl[xi] = l;         // cand split in place
            }
        }
    }
}

// ---------------- final: hc = tanh(xg2·Wu_n + bu); out = z*s + (1-z)*hc ----
__global__ __launch_bounds__(256) void final_kernel(
    const float* __restrict__ emb, const float* __restrict__ b_update,
    const float* __restrict__ st, float* __restrict__ out)
{
    extern __shared__ float sh[];
    float* xg_s = sh;            // 12872
    float* ws   = sh + 12872;    // 6*64 = 384
    float* bu   = ws + 384;      // 64
    float* em   = bu + 64;       // 16

    int n = blockIdx.x, tid = threadIdx.x;
    if (tid < EDIM) em[tid] = emb[n*EDIM + tid];
    __syncthreads();
    if (tid < DOUT) {
        float a = 0.f;
        #pragma unroll
        for (int e = 0; e < EDIM; e++) a += em[e] * b_update[e*DOUT + tid];
        bu[tid] = a;
    }
    const float* r0 = g_X0 + (size_t)n*CCOLS;
    const float* r1 = g_Y1 + (size_t)n*CCOLS;
    const float* r2 = g_Y2 + (size_t)n*CCOLS;
    for (int c = tid; c < CCOLS; c += 256) {
        int b = c / CIN, i = c - b*CIN;
        xg_s[(0*CIN + i)*XGS + b] = r0[c];
        xg_s[(1*CIN + i)*XGS + b] = r1[c];
        xg_s[(2*CIN + i)*XGS + b] = r2[c];
    }
    __syncthreads();

    int tx = tid & 15, ty = tid >> 4;
    float acc[4][4] = {};
    const float* wu = g_Wu + (size_t)n*WUJ;
    for (int kk0 = 0; kk0 < KI; kk0 += 6) {
        __syncthreads();
        for (int idx = tid; idx < 6*DOUT; idx += 256)
            ws[idx] = wu[kk0*DOUT + idx];
        __syncthreads();
        #pragma unroll
        for (int kk = 0; kk < 6; kk++) {
            const float* xr = &xg_s[(kk0 + kk)*XGS + ty*4];
            float a0 = xr[0], a1 = xr[1], a2 = xr[2], a3 = xr[3];
            float4 w0 = *(const float4*)&ws[kk*DOUT + tx*4];
            float w[4] = {w0.x, w0.y, w0.z, w0.w};
            #pragma unroll
            for (int j2 = 0; j2 < 4; j2++) {
                acc[0][j2] += a0 * w[j2];
                acc[1][j2] += a1 * w[j2];
                acc[2][j2] += a2 * w[j2];
                acc[3][j2] += a3 * w[j2];
            }
        }
    }
    __syncthreads();
    #pragma unroll
    for (int bb = 0; bb < 4; bb++) {
        int b = ty*4 + bb;
        #pragma unroll
        for (int oo = 0; oo < 4; oo++) {
            int o = tx*4 + oo;
            float hc = tanhf(acc[bb][oo] + bu[o]);
            float z  = g_Z[((size_t)n*Bb + b)*DOUT + o];
            float s  = st[((size_t)b*Nn + n)*DOUT + o];
            out[((size_t)b*Nn + n)*DOUT + o] = z*s + (1.f - z)*hc;
        }
    }
}

// ---------------- launch ---------------------------------------------------
extern "C" void kernel_launch(void* const* d_in, const int* in_sizes, int n_in,
                              void* d_out, int out_size)
{
    const float* x    = (const float*)d_in[0];
    const float* st   = (const float*)d_in[1];
    const float* emb  = (const float*)d_in[2];
    const float* Wr_w = (const float*)d_in[3];
    const float* Wu_w = (const float*)d_in[4];
    const float* br_b = (const float*)d_in[5];
    const float* bu_b = (const float*)d_in[6];
    float* out = (float*)d_out;

    bf16 *pAh, *pAl, *pXh, *pXl, *pY1h, *pY1l;
    float *pX0, *pY1, *pY2, *pWr, *pWu;
    cudaGetSymbolAddress((void**)&pAh,  g_Ah);
    cudaGetSymbolAddress((void**)&pAl,  g_Al);
    cudaGetSymbolAddress((void**)&pX0,  g_X0);
    cudaGetSymbolAddress((void**)&pXh,  g_Xh);
    cudaGetSymbolAddress((void**)&pXl,  g_Xl);
    cudaGetSymbolAddress((void**)&pY1,  g_Y1);
    cudaGetSymbolAddress((void**)&pY1h, g_Y1h);
    cudaGetSymbolAddress((void**)&pY1l, g_Y1l);
    cudaGetSymbolAddress((void**)&pY2,  g_Y2);
    cudaGetSymbolAddress((void**)&pWr,  g_Wr);
    cudaGetSymbolAddress((void**)&pWu,  g_Wu);

    const int gate_smem  = (12872 + 768 + 128 + 16) * 4;
    const int final_smem = (12872 + 384 + 64 + 16) * 4;
    cudaFuncSetAttribute(gate_kernel,  cudaFuncAttributeMaxDynamicSharedMemorySize, gate_smem);
    cudaFuncSetAttribute(final_kernel, cudaFuncAttributeMaxDynamicSharedMemorySize, final_smem);
    cudaFuncSetAttribute(mma_gemm,     cudaFuncAttributeMaxDynamicSharedMemorySize, GSMEM_B);

    dim3 gGemm(CCOLS/128, (Nn + 127)/128);   // (33, 16)

    // adjacency + per-node weights (independent of conv)
    adj_softmax<<<Nn, 256>>>(emb);
    mix_weights<<<dim3((WRJ + 255)/256, (Nn + 31)/32), 256>>>(emb, Wr_w, pWr, WRJ);
    mix_weights<<<dim3((WUJ + 255)/256, (Nn + 31)/32), 256>>>(emb, Wu_w, pWu, WUJ);

    // pass 1: conv of xs
    pack_x0<<<(Nn*CCOLS + 255)/256, 256>>>(x, st);
    mma_gemm<<<gGemm, 256, GSMEM_B>>>(pAh, pAl, pXh, pXl, pX0, pY1, pY1h, pY1l,
                                      Nn, CCOLS, Nn, 1.f, 0.f, 1);
    mma_gemm<<<gGemm, 256, GSMEM_B>>>(pAh, pAl, pY1h, pY1l, pX0, pY2, pY1h, pY1l,
                                      Nn, CCOLS, Nn, 2.f, -1.f, 0);

    // gates: z, r; writes cand (fp32 + split) into X0/Xh/Xl in place
    gate_kernel<<<Nn, 256, gate_smem>>>(emb, br_b, st);

    // pass 2: conv of cand
    mma_gemm<<<gGemm, 256, GSMEM_B>>>(pAh, pAl, pXh, pXl, pX0, pY1, pY1h, pY1l,
                                      Nn, CCOLS, Nn, 1.f, 0.f, 1);
    mma_gemm<<<gGemm, 256, GSMEM_B>>>(pAh, pAl, pY1h, pY1l, pX0, pY2, pY1h, pY1l,
                                      Nn, CCOLS, Nn, 2.f, -1.f, 0);

    // candidate + combine
    final_kernel<<<Nn, 256, final_smem>>>(emb, bu_b, st, out);
}